// round 3
// baseline (speedup 1.0000x reference)
#include <cuda_runtime.h>
#include <cuda_bf16.h>
#include <cstddef>

// Problem constants
#define BB   8
#define CIN  64
#define COUT 64
#define HH   256
#define WW   256
#define KK   3

// Tiling
#define TH 8            // output rows per CTA
#define TW 32           // output cols per CTA
#define CC 8            // input-channel chunk held in smem
#define NTHREADS 256

// Pre-scaled weights: layout [b][ci][r][co], r = kh*3+kw  (8*64*9*64 floats = 1.18 MB)
__device__ float g_wscaled[BB * CIN * 9 * COUT];

// ---------------------------------------------------------------------------
// Kernel 1: fold alpha into weights.
// g_wscaled[((b*CIN+ci)*9+r)*COUT+co] = weight[((co*CIN+ci)*9)+r] * alpha[b*CIN+ci]
// ---------------------------------------------------------------------------
__global__ void scale_weights_kernel(const float* __restrict__ weight,
                                     const float* __restrict__ alpha) {
    int idx = blockIdx.x * blockDim.x + threadIdx.x;          // 0 .. 294911
    if (idx >= BB * CIN * 9 * COUT) return;
    int co = idx & 63;
    int t  = idx >> 6;          // (b*CIN+ci)*9 + r
    int r  = t % 9;
    int bc = t / 9;             // b*CIN + ci
    int ci = bc & 63;
    float w = weight[(co * CIN + ci) * 9 + r];
    g_wscaled[idx] = w * alpha[bc];
}

// ---------------------------------------------------------------------------
// Kernel 2: direct conv, register-blocked.
// Grid: (WW/TW, HH/TH, B).  Block: 256 threads.
// Thread tid: pix = tid&31 (w offset within tile), cog = tid>>5 (cout group of 8).
// Each thread: acc[8 couts][8 rows] for its fixed w column.
// ---------------------------------------------------------------------------
__global__ __launch_bounds__(NTHREADS, 2)
void spec_ada_conv_kernel(const float* __restrict__ x,
                          const float* __restrict__ bias,
                          float* __restrict__ out) {
    __shared__ float in_s[CC][TH + 2][TW + 2];        // 8*10*34  = 10880 B
    __shared__ float w_s[CC * 9][COUT];               // 72*64    = 18432 B

    const int tid = threadIdx.x;
    const int pix = tid & 31;        // w within tile
    const int cog = tid >> 5;        // 0..7
    const int co0 = cog * 8;

    const int b  = blockIdx.z;
    const int h0 = blockIdx.y * TH;
    const int w0 = blockIdx.x * TW;

    float acc[8][8];
#pragma unroll
    for (int i = 0; i < 8; ++i) {
        float bv = bias[co0 + i];
#pragma unroll
        for (int j = 0; j < 8; ++j) acc[i][j] = bv;
    }

    const int NCHUNK = CIN / CC;     // 8
    for (int cc = 0; cc < NCHUNK; ++cc) {
        const int ci0 = cc * CC;

        // ---- load input halo tile: CC * 10 * 34 = 2720 elements ----
        for (int idx = tid; idx < CC * (TH + 2) * (TW + 2); idx += NTHREADS) {
            int ci  = idx / ((TH + 2) * (TW + 2));
            int rem = idx % ((TH + 2) * (TW + 2));
            int hh  = rem / (TW + 2);
            int ww  = rem % (TW + 2);
            int gh = h0 + hh - 1;
            int gw = w0 + ww - 1;
            float v = 0.0f;
            if (gh >= 0 && gh < HH && gw >= 0 && gw < WW) {
                v = x[(((size_t)b * CIN + ci0 + ci) * HH + gh) * WW + gw];
            }
            in_s[ci][hh][ww] = v;
        }

        // ---- load pre-scaled weight chunk: CC*9*64 = 4608 elements (coalesced) ----
        {
            const float* wsrc = &g_wscaled[((size_t)(b * CIN + ci0) * 9) * COUT];
            float* wdst = &w_s[0][0];
            for (int idx = tid; idx < CC * 9 * COUT; idx += NTHREADS) {
                wdst[idx] = wsrc[idx];
            }
        }
        __syncthreads();

        // ---- compute ----
        for (int ci = 0; ci < CC; ++ci) {
#pragma unroll
            for (int r = 0; r < 9; ++r) {
                const int kh = r / 3;
                const int kw = r % 3;

                // weight fragment: warp-uniform address -> broadcast
                float4 wa = *(const float4*)&w_s[ci * 9 + r][co0];
                float4 wb = *(const float4*)&w_s[ci * 9 + r][co0 + 4];
                float wf[8] = {wa.x, wa.y, wa.z, wa.w, wb.x, wb.y, wb.z, wb.w};

                // input fragment: 8 rows at this thread's column (stride-1 across lanes)
                float xf[8];
#pragma unroll
                for (int j = 0; j < 8; ++j) {
                    xf[j] = in_s[ci][j + kh][pix + kw];
                }

#pragma unroll
                for (int i = 0; i < 8; ++i) {
#pragma unroll
                    for (int j = 0; j < 8; ++j) {
                        acc[i][j] += wf[i] * xf[j];
                    }
                }
            }
        }
        __syncthreads();
    }

    // ---- store: warp writes 32 consecutive pixels -> 128B coalesced ----
#pragma unroll
    for (int i = 0; i < 8; ++i) {
#pragma unroll
        for (int j = 0; j < 8; ++j) {
            out[(((size_t)b * COUT + co0 + i) * HH + (h0 + j)) * WW + w0 + pix] =
                acc[i][j];
        }
    }
}

// ---------------------------------------------------------------------------
// Launch. Inputs (metadata order): x, alpha, weight, bias. Output: float32.
// ---------------------------------------------------------------------------
extern "C" void kernel_launch(void* const* d_in, const int* in_sizes, int n_in,
                              void* d_out, int out_size) {
    const float* x      = (const float*)d_in[0];
    const float* alpha  = (const float*)d_in[1];
    const float* weight = (const float*)d_in[2];
    const float* bias   = (const float*)d_in[3];
    float* out = (float*)d_out;

    (void)in_sizes; (void)n_in; (void)out_size;

    // 1) fold alpha into weights
    {
        int n = BB * CIN * 9 * COUT;                  // 294912
        scale_weights_kernel<<<(n + 255) / 256, 256>>>(weight, alpha);
    }

    // 2) conv
    {
        dim3 grid(WW / TW, HH / TH, BB);              // (8, 32, 8)
        spec_ada_conv_kernel<<<grid, NTHREADS>>>(x, bias, out);
    }
}

// round 4
// speedup vs baseline: 1.1167x; 1.1167x over previous
#include <cuda_runtime.h>
#include <cuda_bf16.h>
#include <cstddef>

// Problem constants
#define BB   8
#define CIN  64
#define COUT 64
#define HH   256
#define WW   256
#define KK   3

// Tiling
#define TH 8            // output rows per CTA
#define TW 32           // output cols per CTA
#define CC 8            // input-channel chunk held in smem
#define NTHREADS 256

// Pre-scaled weights: layout [b][ci][r][co], r = kh*3+kw  (8*64*9*64 floats = 1.18 MB)
__device__ float g_wscaled[BB * CIN * 9 * COUT];

// ---------------------------------------------------------------------------
// Packed fp32x2 helpers (sm_100+): FFMA2 via PTX — ptxas never auto-fuses.
// ---------------------------------------------------------------------------
__device__ __forceinline__ void ffma2(unsigned long long& d,
                                      unsigned long long a,
                                      unsigned long long b) {
    asm("fma.rn.f32x2 %0, %1, %2, %0;" : "+l"(d) : "l"(a), "l"(b));
}
__device__ __forceinline__ unsigned long long dup2(float x) {
    unsigned long long r;
    asm("mov.b64 %0, {%1, %1};" : "=l"(r) : "f"(x));
    return r;
}
__device__ __forceinline__ unsigned long long pack2(float lo, float hi) {
    unsigned long long r;
    asm("mov.b64 %0, {%1, %2};" : "=l"(r) : "f"(lo), "f"(hi));
    return r;
}
__device__ __forceinline__ void unpack2(unsigned long long v, float& lo, float& hi) {
    asm("mov.b64 {%0, %1}, %2;" : "=f"(lo), "=f"(hi) : "l"(v));
}

// ---------------------------------------------------------------------------
// Kernel 1: fold alpha into weights.
// ---------------------------------------------------------------------------
__global__ void scale_weights_kernel(const float* __restrict__ weight,
                                     const float* __restrict__ alpha) {
    int idx = blockIdx.x * blockDim.x + threadIdx.x;          // 0 .. 294911
    if (idx >= BB * CIN * 9 * COUT) return;
    int co = idx & 63;
    int t  = idx >> 6;          // (b*CIN+ci)*9 + r
    int r  = t % 9;
    int bc = t / 9;             // b*CIN + ci
    int ci = bc & 63;
    float w = weight[(co * CIN + ci) * 9 + r];
    g_wscaled[idx] = w * alpha[bc];
}

// ---------------------------------------------------------------------------
// Kernel 2: direct conv, register-blocked, packed f32x2 FMA.
// Grid: (WW/TW, HH/TH, B).  Block: 256 threads.
// Thread: pix = tid&31 (w col), cog = tid>>5 -> 8 couts (4 packed pairs).
// acc2[i2][j]: pair (co0+2*i2, co0+2*i2+1) x 8 output rows.
// ---------------------------------------------------------------------------
__global__ __launch_bounds__(NTHREADS, 2)
void spec_ada_conv_kernel(const float* __restrict__ x,
                          const float* __restrict__ bias,
                          float* __restrict__ out) {
    __shared__ float in_s[CC][TH + 2][TW + 2];        // 8*10*34  = 10880 B
    __shared__ float w_s[CC * 9][COUT];               // 72*64    = 18432 B

    const int tid = threadIdx.x;
    const int pix = tid & 31;        // w within tile
    const int cog = tid >> 5;        // 0..7
    const int co0 = cog * 8;

    const int b  = blockIdx.z;
    const int h0 = blockIdx.y * TH;
    const int w0 = blockIdx.x * TW;

    // 4 cout-pairs x 8 rows of packed fp32x2 accumulators (64 regs)
    unsigned long long acc2[4][8];
#pragma unroll
    for (int i2 = 0; i2 < 4; ++i2) {
        unsigned long long bv = pack2(bias[co0 + 2 * i2], bias[co0 + 2 * i2 + 1]);
#pragma unroll
        for (int j = 0; j < 8; ++j) acc2[i2][j] = bv;
    }

    const int NCHUNK = CIN / CC;     // 8
    for (int cc = 0; cc < NCHUNK; ++cc) {
        const int ci0 = cc * CC;

        // ---- load input halo tile: CC * 10 * 34 = 2720 elements ----
        for (int idx = tid; idx < CC * (TH + 2) * (TW + 2); idx += NTHREADS) {
            int ci  = idx / ((TH + 2) * (TW + 2));
            int rem = idx % ((TH + 2) * (TW + 2));
            int hh  = rem / (TW + 2);
            int ww  = rem % (TW + 2);
            int gh = h0 + hh - 1;
            int gw = w0 + ww - 1;
            float v = 0.0f;
            if (gh >= 0 && gh < HH && gw >= 0 && gw < WW) {
                v = x[(((size_t)b * CIN + ci0 + ci) * HH + gh) * WW + gw];
            }
            in_s[ci][hh][ww] = v;
        }

        // ---- load pre-scaled weight chunk (vectorized, coalesced) ----
        {
            const float4* wsrc =
                (const float4*)&g_wscaled[((size_t)(b * CIN + ci0) * 9) * COUT];
            float4* wdst = (float4*)&w_s[0][0];
            for (int idx = tid; idx < CC * 9 * COUT / 4; idx += NTHREADS) {
                wdst[idx] = wsrc[idx];
            }
        }
        __syncthreads();

        // ---- compute: kw-outer so the 10-row input column is loaded once ----
#pragma unroll 1
        for (int ci = 0; ci < CC; ++ci) {
#pragma unroll
            for (int kw = 0; kw < 3; ++kw) {
                // 10 input rows at this thread's column, duplicated into f32x2
                unsigned long long xd[10];
#pragma unroll
                for (int rr = 0; rr < 10; ++rr) {
                    xd[rr] = dup2(in_s[ci][rr][pix + kw]);
                }

#pragma unroll
                for (int kh = 0; kh < 3; ++kh) {
                    const int r = kh * 3 + kw;
                    // weight pairs: 2x ulonglong2 (16B, co0 is 32B-aligned)
                    ulonglong2 wpa = *(const ulonglong2*)&w_s[ci * 9 + r][co0];
                    ulonglong2 wpb = *(const ulonglong2*)&w_s[ci * 9 + r][co0 + 4];
                    unsigned long long wp[4] = {wpa.x, wpa.y, wpb.x, wpb.y};

#pragma unroll
                    for (int i2 = 0; i2 < 4; ++i2) {
#pragma unroll
                        for (int j = 0; j < 8; ++j) {
                            ffma2(acc2[i2][j], wp[i2], xd[j + kh]);
                        }
                    }
                }
            }
        }
        __syncthreads();
    }

    // ---- store: warp writes 32 consecutive pixels -> 128B coalesced ----
#pragma unroll
    for (int i2 = 0; i2 < 4; ++i2) {
#pragma unroll
        for (int j = 0; j < 8; ++j) {
            float lo, hi;
            unpack2(acc2[i2][j], lo, hi);
            size_t base =
                (((size_t)b * COUT + co0 + 2 * i2) * HH + (h0 + j)) * WW + w0 + pix;
            out[base] = lo;
            out[base + (size_t)HH * WW] = hi;
        }
    }
}

// ---------------------------------------------------------------------------
// Launch. Inputs (metadata order): x, alpha, weight, bias. Output: float32.
// ---------------------------------------------------------------------------
extern "C" void kernel_launch(void* const* d_in, const int* in_sizes, int n_in,
                              void* d_out, int out_size) {
    const float* x      = (const float*)d_in[0];
    const float* alpha  = (const float*)d_in[1];
    const float* weight = (const float*)d_in[2];
    const float* bias   = (const float*)d_in[3];
    float* out = (float*)d_out;

    (void)in_sizes; (void)n_in; (void)out_size;

    // 1) fold alpha into weights
    {
        int n = BB * CIN * 9 * COUT;                  // 294912
        scale_weights_kernel<<<(n + 255) / 256, 256>>>(weight, alpha);
    }

    // 2) conv
    {
        dim3 grid(WW / TW, HH / TH, BB);              // (8, 32, 8)
        spec_ada_conv_kernel<<<grid, NTHREADS>>>(x, bias, out);
    }
}

// round 6
// speedup vs baseline: 2.2554x; 2.0196x over previous
#include <cuda_runtime.h>
#include <cuda_bf16.h>
#include <cstdint>
#include <cstddef>

// Problem constants
#define BB   8
#define CIN  64
#define COUT 64
#define HH   256
#define WW   256

// ---------------------------------------------------------------------------
// Device scratch (allocation-free rule: __device__ globals)
// ---------------------------------------------------------------------------
__device__ __nv_bfloat16 g_xhi[(size_t)BB * HH * WW * CIN];    // 64 MB, NHWC hi
__device__ __nv_bfloat16 g_xlo[(size_t)BB * HH * WW * CIN];    // 64 MB, NHWC lo
__device__ __nv_bfloat16 g_w[(size_t)BB * 9 * 2 * COUT * CIN]; // [b][tap][split][co][ci]

// ---------------------------------------------------------------------------
// Helpers
// ---------------------------------------------------------------------------
__device__ __forceinline__ uint32_t smem_u32(const void* p) {
    uint32_t a;
    asm("{ .reg .u64 t; cvta.to.shared.u64 t, %1; cvt.u32.u64 %0, t; }"
        : "=r"(a) : "l"(p));
    return a;
}
#define SWZ(o) ((o) ^ (((o) >> 3) & 0x70))

#define STS128(a, v) \
    asm volatile("st.shared.v4.b32 [%0], {%1,%2,%3,%4};" \
                 :: "r"(a), "r"((v).x), "r"((v).y), "r"((v).z), "r"((v).w) : "memory")

#define LDSM4(r0, r1, r2, r3, a) \
    asm volatile("ldmatrix.sync.aligned.m8n8.x4.shared.b16 {%0,%1,%2,%3}, [%4];" \
                 : "=r"(r0), "=r"(r1), "=r"(r2), "=r"(r3) : "r"(a))

__device__ __forceinline__ void mma16816(float* c, const uint32_t* a,
                                         const uint32_t* b) {
    asm volatile(
        "mma.sync.aligned.m16n8k16.row.col.f32.bf16.bf16.f32 "
        "{%0,%1,%2,%3}, {%4,%5,%6,%7}, {%8,%9}, {%0,%1,%2,%3};"
        : "+f"(c[0]), "+f"(c[1]), "+f"(c[2]), "+f"(c[3])
        : "r"(a[0]), "r"(a[1]), "r"(a[2]), "r"(a[3]), "r"(b[0]), "r"(b[1]));
}

// ---------------------------------------------------------------------------
// Pre-pass 1: x NCHW fp32 -> NHWC bf16 hi/lo.  grid (256 h, 8 b), 256 thr.
// ---------------------------------------------------------------------------
__global__ void xcvt_kernel(const float* __restrict__ x) {
    __shared__ float tile[64][65];
    const int h = blockIdx.x, b = blockIdx.y;
    const int t = threadIdx.x;
    for (int w0 = 0; w0 < WW; w0 += 64) {
        {
            const int ci0 = t >> 6, w = t & 63;
#pragma unroll
            for (int k = 0; k < 16; ++k) {
                int ci = ci0 + k * 4;
                tile[ci][w] = x[(((size_t)b * CIN + ci) * HH + h) * WW + w0 + w];
            }
        }
        __syncthreads();
        {
            const int ci = t & 63, p0 = t >> 6;
#pragma unroll
            for (int m = 0; m < 16; ++m) {
                int p = p0 + m * 4;
                float v = tile[ci][p];
                __nv_bfloat16 hi = __float2bfloat16(v);
                __nv_bfloat16 lo = __float2bfloat16(v - __bfloat162float(hi));
                size_t o = (((size_t)b * HH + h) * WW + w0 + p) * CIN + ci;
                g_xhi[o] = hi;
                g_xlo[o] = lo;
            }
        }
        __syncthreads();
    }
}

// ---------------------------------------------------------------------------
// Pre-pass 2: alpha-folded weights -> [b][tap][split][co][ci] bf16 hi/lo.
// ---------------------------------------------------------------------------
__global__ void wcvt_kernel(const float* __restrict__ weight,
                            const float* __restrict__ alpha) {
    int idx = blockIdx.x * 256 + threadIdx.x;
    if (idx >= BB * 9 * COUT * CIN) return;
    int ci = idx & 63;
    int co = (idx >> 6) & 63;
    int rest = idx >> 12;         // b*9 + tap
    float v = weight[(co * CIN + ci) * 9 + rest % 9] * alpha[(rest / 9) * CIN + ci];
    __nv_bfloat16 hi = __float2bfloat16(v);
    __nv_bfloat16 lo = __float2bfloat16(v - __bfloat162float(hi));
    g_w[(size_t)(rest * 2 + 0) * 4096 + co * 64 + ci] = hi;
    g_w[(size_t)(rest * 2 + 1) * 4096 + co * 64 + ci] = lo;
}

// ---------------------------------------------------------------------------
// Main conv: mma.sync bf16 implicit GEMM.
// CTA: 2 h-rows x 128 w x 64 cout.  grid (2, 128, 8).  256 thr = 8 warps.
// Warp w: h-row = w>>2, w-chunk = (w&3)*32; owns 32 px x 64 co.
// SMEM (1024-aligned base):
//   A: 8 bufs (4 halo lines x {hi,lo}), 130 rows x 128B, padded to 17408B
//   B: 2 tap-parity bufs x 16384B (hi at +0, lo at +8192)
//   bias: 256B
// ---------------------------------------------------------------------------
#define ABUF     17408
#define SM_B     (8 * ABUF)            // 139264
#define SM_BIAS  (SM_B + 32768)        // 172032
#define SMEM_REQ (SM_BIAS + 256 + 1024)

__global__ __launch_bounds__(256, 1)
void conv_mma_kernel(const float* __restrict__ bias, float* __restrict__ out) {
    extern __shared__ char smem_raw[];
    const uint32_t sraw = smem_u32(smem_raw);
    const uint32_t sb = (sraw + 1023) & ~1023u;
    char* g = smem_raw + (sb - sraw);

    const int tid = threadIdx.x;
    const int warp = tid >> 5;
    const int lane = tid & 31;
    const int b = blockIdx.z;
    const int h0 = blockIdx.y * 2;
    const int w0 = blockIdx.x * 128;

    if (tid < 64) ((float*)(g + SM_BIAS))[tid] = bias[tid];

    // ---- load 4 halo lines (hi+lo): 130 rows x 64ci, SW128-swizzled ----
    {
        const int c8 = tid & 7;        // 16B ci-group
        const int jr = tid >> 3;       // 0..31
        for (int l = 0; l < 4; ++l) {
            const int gh = h0 + l - 1;
            const bool hok = (gh >= 0) && (gh < HH);
            const uint32_t bh = sb + (l * 2 + 0) * ABUF;
            const uint32_t bl = sb + (l * 2 + 1) * ABUF;
#pragma unroll
            for (int it = 0; it < 5; ++it) {
                int j = it * 32 + jr;          // 0..159
                if (j < 130) {
                    int gw = w0 - 1 + j;
                    uint4 vh = make_uint4(0, 0, 0, 0), vl = make_uint4(0, 0, 0, 0);
                    if (hok && gw >= 0 && gw < WW) {
                        size_t o = (((size_t)b * HH + gh) * WW + gw) * CIN + c8 * 8;
                        vh = *(const uint4*)&g_xhi[o];
                        vl = *(const uint4*)&g_xlo[o];
                    }
                    uint32_t so = SWZ((uint32_t)(j * 128 + c8 * 16));
                    STS128(bh + so, vh);
                    STS128(bl + so, vl);
                }
            }
        }
    }

    // ---- load B for tap 0 into buffer 0 ----
    {
        const char* src = (const char*)g_w + (size_t)(b * 9) * 16384;
#pragma unroll
        for (int i = 0; i < 4; ++i) {
            uint32_t o = (uint32_t)(i * 256 + tid) * 16;
            uint4 v = *(const uint4*)(src + o);
            STS128(sb + SM_B + (o & 8192) + SWZ(o & 8191), v);
        }
    }
    __syncthreads();

    // ---- accumulators, bias-initialized ----
    float acc[2][8][4];
    {
        const float* biasS = (const float*)(g + SM_BIAS);
#pragma unroll
        for (int nb = 0; nb < 8; ++nb) {
            float b0 = biasS[nb * 8 + (lane & 3) * 2];
            float b1 = biasS[nb * 8 + (lane & 3) * 2 + 1];
#pragma unroll
            for (int mh = 0; mh < 2; ++mh) {
                acc[mh][nb][0] = b0; acc[mh][nb][1] = b1;
                acc[mh][nb][2] = b0; acc[mh][nb][3] = b1;
            }
        }
    }

    // per-lane ldmatrix address components
    const int arow = lane & 15;
    const uint32_t acoff = (uint32_t)(lane >> 4) * 16;
    const int brow = (lane & 7) + (lane >> 4) * 8;
    const uint32_t bcoff = (uint32_t)((lane >> 3) & 1) * 16;
    const int wbase = (warp & 3) * 32;
    const int lline = warp >> 2;

    for (int tap = 0; tap < 9; ++tap) {
        const int cur = tap & 1;
        const int kh = tap / 3, kw = tap - kh * 3;

        // prefetch next tap's B into registers
        uint4 pf[4];
        if (tap < 8) {
            const char* src = (const char*)g_w + (size_t)(b * 9 + tap + 1) * 16384;
#pragma unroll
            for (int i = 0; i < 4; ++i)
                pf[i] = *(const uint4*)(src + (uint32_t)(i * 256 + tid) * 16);
        }

        const uint32_t aH = sb + (uint32_t)((lline + kh) * 2 + 0) * ABUF;
        const uint32_t aL = aH + ABUF;
        const uint32_t bH = sb + SM_B + (uint32_t)cur * 16384;
        const uint32_t bL = bH + 8192;
        const int r0 = wbase + kw + arow;       // + mh*16, max 129

#pragma unroll
        for (int kc = 0; kc < 4; ++kc) {
            const uint32_t co = (uint32_t)kc * 32 + acoff;
            uint32_t ah[2][4], al[2][4];
#pragma unroll
            for (int mh = 0; mh < 2; ++mh) {
                uint32_t off = SWZ((uint32_t)((r0 + mh * 16) * 128) + co);
                LDSM4(ah[mh][0], ah[mh][1], ah[mh][2], ah[mh][3], aH + off);
                LDSM4(al[mh][0], al[mh][1], al[mh][2], al[mh][3], aL + off);
            }
#pragma unroll
            for (int nb2 = 0; nb2 < 4; ++nb2) {
                uint32_t boff =
                    SWZ((uint32_t)((nb2 * 16 + brow) * 128) + (uint32_t)kc * 32 + bcoff);
                uint32_t bh[4], bl[4];
                LDSM4(bh[0], bh[1], bh[2], bh[3], bH + boff);
                LDSM4(bl[0], bl[1], bl[2], bl[3], bL + boff);
#pragma unroll
                for (int mh = 0; mh < 2; ++mh) {
                    mma16816(acc[mh][2 * nb2],     ah[mh], bh);       // Ah*Bh
                    mma16816(acc[mh][2 * nb2 + 1], ah[mh], bh + 2);
                    mma16816(acc[mh][2 * nb2],     ah[mh], bl);       // Ah*Bl
                    mma16816(acc[mh][2 * nb2 + 1], ah[mh], bl + 2);
                    mma16816(acc[mh][2 * nb2],     al[mh], bh);       // Al*Bh
                    mma16816(acc[mh][2 * nb2 + 1], al[mh], bh + 2);
                }
            }
        }

        if (tap < 8) {
            // store prefetched B into the other buffer; one sync per tap
#pragma unroll
            for (int i = 0; i < 4; ++i) {
                uint32_t o = (uint32_t)(i * 256 + tid) * 16;
                STS128(sb + SM_B + (uint32_t)(cur ^ 1) * 16384 + (o & 8192) +
                           SWZ(o & 8191),
                       pf[i]);
            }
            __syncthreads();
        }
    }

    // ---- epilogue: direct stores (32B sectors fully utilized) ----
    const int hgl = h0 + (warp >> 2);
#pragma unroll
    for (int mh = 0; mh < 2; ++mh) {
        const int wgl = w0 + wbase + mh * 16 + (lane >> 2);
#pragma unroll
        for (int nb = 0; nb < 8; ++nb) {
            const int n0 = nb * 8 + (lane & 3) * 2;
            float* p = out + (((size_t)b * COUT + n0) * HH + hgl) * WW + wgl;
            p[0] = acc[mh][nb][0];
            p[(size_t)HH * WW] = acc[mh][nb][1];
            p[8] = acc[mh][nb][2];
            p[(size_t)HH * WW + 8] = acc[mh][nb][3];
        }
    }
}

// ---------------------------------------------------------------------------
// Launch. Inputs: x, alpha, weight, bias. Output: float32 NCHW.
// ---------------------------------------------------------------------------
extern "C" void kernel_launch(void* const* d_in, const int* in_sizes, int n_in,
                              void* d_out, int out_size) {
    const float* x      = (const float*)d_in[0];
    const float* alpha  = (const float*)d_in[1];
    const float* weight = (const float*)d_in[2];
    const float* bias   = (const float*)d_in[3];
    float* out = (float*)d_out;
    (void)in_sizes; (void)n_in; (void)out_size;

    cudaFuncSetAttribute(conv_mma_kernel,
                         cudaFuncAttributeMaxDynamicSharedMemorySize, SMEM_REQ);

    xcvt_kernel<<<dim3(HH, BB), 256>>>(x);
    {
        int n = BB * 9 * COUT * CIN;
        wcvt_kernel<<<(n + 255) / 256, 256>>>(weight, alpha);
    }
    conv_mma_kernel<<<dim3(2, 128, BB), 256, SMEM_REQ>>>(bias, out);
}

// round 7
// speedup vs baseline: 2.4164x; 1.0714x over previous
#include <cuda_runtime.h>
#include <cuda_bf16.h>
#include <cstdint>
#include <cstddef>

// Problem constants
#define BB   8
#define CIN  64
#define COUT 64
#define HH   256
#define WW   256

// ---------------------------------------------------------------------------
// Device scratch (allocation-free rule: __device__ globals)
// ---------------------------------------------------------------------------
__device__ __nv_bfloat16 g_xhi[(size_t)BB * HH * WW * CIN];    // 64 MB, NHWC hi
__device__ __nv_bfloat16 g_xlo[(size_t)BB * HH * WW * CIN];    // 64 MB, NHWC lo
__device__ __nv_bfloat16 g_w[(size_t)BB * 9 * 2 * COUT * CIN]; // [b][tap][split][co][ci]

// ---------------------------------------------------------------------------
// Helpers
// ---------------------------------------------------------------------------
__device__ __forceinline__ uint32_t smem_u32(const void* p) {
    uint32_t a;
    asm("{ .reg .u64 t; cvta.to.shared.u64 t, %1; cvt.u32.u64 %0, t; }"
        : "=r"(a) : "l"(p));
    return a;
}
#define SWZ(o) ((o) ^ (((o) >> 3) & 0x70))

#define STS128(a, v) \
    asm volatile("st.shared.v4.b32 [%0], {%1,%2,%3,%4};" \
                 :: "r"(a), "r"((v).x), "r"((v).y), "r"((v).z), "r"((v).w) : "memory")

#define LDSM4(r0, r1, r2, r3, a) \
    asm volatile("ldmatrix.sync.aligned.m8n8.x4.shared.b16 {%0,%1,%2,%3}, [%4];" \
                 : "=r"(r0), "=r"(r1), "=r"(r2), "=r"(r3) : "r"(a))

__device__ __forceinline__ void mma16816(float* c, const uint32_t* a,
                                         const uint32_t* b) {
    asm volatile(
        "mma.sync.aligned.m16n8k16.row.col.f32.bf16.bf16.f32 "
        "{%0,%1,%2,%3}, {%4,%5,%6,%7}, {%8,%9}, {%0,%1,%2,%3};"
        : "+f"(c[0]), "+f"(c[1]), "+f"(c[2]), "+f"(c[3])
        : "r"(a[0]), "r"(a[1]), "r"(a[2]), "r"(a[3]), "r"(b[0]), "r"(b[1]));
}

// ---------------------------------------------------------------------------
// Pre-pass 1: x NCHW fp32 -> NHWC bf16 hi/lo.  grid (256 h, 8 b), 256 thr.
// Phase 2 packs 8 channels per thread -> STG.128, coalesced across c8 lanes.
// ---------------------------------------------------------------------------
__global__ void xcvt_kernel(const float* __restrict__ x) {
    __shared__ float tile[64][65];
    const int h = blockIdx.x, b = blockIdx.y;
    const int t = threadIdx.x;
    for (int w0 = 0; w0 < WW; w0 += 64) {
        {
            const int ci0 = t >> 6, w = t & 63;
#pragma unroll
            for (int k = 0; k < 16; ++k) {
                int ci = ci0 + k * 4;
                tile[ci][w] = x[(((size_t)b * CIN + ci) * HH + h) * WW + w0 + w];
            }
        }
        __syncthreads();
        {
            const int c8 = t & 7;        // channel-octet
            const int p0 = t >> 3;       // 0..31
#pragma unroll
            for (int m = 0; m < 2; ++m) {
                const int p = p0 + m * 32;
                uint32_t hi4[4], lo4[4];
#pragma unroll
                for (int jj = 0; jj < 4; ++jj) {
                    float v0 = tile[c8 * 8 + jj * 2][p];
                    float v1 = tile[c8 * 8 + jj * 2 + 1][p];
                    __nv_bfloat16 h0 = __float2bfloat16(v0);
                    __nv_bfloat16 h1 = __float2bfloat16(v1);
                    __nv_bfloat16 l0 = __float2bfloat16(v0 - __bfloat162float(h0));
                    __nv_bfloat16 l1 = __float2bfloat16(v1 - __bfloat162float(h1));
                    hi4[jj] = (uint32_t)*(uint16_t*)&h0 |
                              ((uint32_t)*(uint16_t*)&h1 << 16);
                    lo4[jj] = (uint32_t)*(uint16_t*)&l0 |
                              ((uint32_t)*(uint16_t*)&l1 << 16);
                }
                size_t o = (((size_t)b * HH + h) * WW + w0 + p) * CIN + c8 * 8;
                *(uint4*)&g_xhi[o] = make_uint4(hi4[0], hi4[1], hi4[2], hi4[3]);
                *(uint4*)&g_xlo[o] = make_uint4(lo4[0], lo4[1], lo4[2], lo4[3]);
            }
        }
        __syncthreads();
    }
}

// ---------------------------------------------------------------------------
// Pre-pass 2: alpha-folded weights -> [b][tap][split][co][ci] bf16 hi/lo.
// ---------------------------------------------------------------------------
__global__ void wcvt_kernel(const float* __restrict__ weight,
                            const float* __restrict__ alpha) {
    int idx = blockIdx.x * 256 + threadIdx.x;
    if (idx >= BB * 9 * COUT * CIN) return;
    int ci = idx & 63;
    int co = (idx >> 6) & 63;
    int rest = idx >> 12;         // b*9 + tap
    float v = weight[(co * CIN + ci) * 9 + rest % 9] * alpha[(rest / 9) * CIN + ci];
    __nv_bfloat16 hi = __float2bfloat16(v);
    __nv_bfloat16 lo = __float2bfloat16(v - __bfloat162float(hi));
    g_w[(size_t)(rest * 2 + 0) * 4096 + co * 64 + ci] = hi;
    g_w[(size_t)(rest * 2 + 1) * 4096 + co * 64 + ci] = lo;
}

// ---------------------------------------------------------------------------
// Main conv: mma.sync bf16 implicit GEMM, 512 threads = 16 warps (4/SMSP).
// CTA: 2 h-rows x 128 w x 64 cout.  grid (2, 128, 8).
// Warp: cohalf = warp&1 (32 co), wchunk = (warp>>1)&3 (32 px), hline = warp>>3.
// Split accumulators: accP = Ah*Bh, accQ = Ah*Bl + Al*Bh (shorter dep chains).
// SMEM (1024-aligned base):
//   A: 8 bufs (4 halo lines x {hi,lo}), 130 rows x 128B, padded to 17408B
//   B: 2 tap-parity bufs x 16384B (hi at +0, lo at +8192)
//   bias: 256B
// ---------------------------------------------------------------------------
#define ABUF     17408
#define SM_B     (8 * ABUF)            // 139264
#define SM_BIAS  (SM_B + 32768)        // 172032
#define SMEM_REQ (SM_BIAS + 256 + 1024)
#define NTH      512

__global__ __launch_bounds__(NTH, 1)
void conv_mma_kernel(const float* __restrict__ bias, float* __restrict__ out) {
    extern __shared__ char smem_raw[];
    const uint32_t sraw = smem_u32(smem_raw);
    const uint32_t sb = (sraw + 1023) & ~1023u;
    char* g = smem_raw + (sb - sraw);

    const int tid = threadIdx.x;
    const int warp = tid >> 5;
    const int lane = tid & 31;
    const int b = blockIdx.z;
    const int h0 = blockIdx.y * 2;
    const int w0 = blockIdx.x * 128;

    const int cohalf = warp & 1;
    const int wchunk = (warp >> 1) & 3;
    const int hline = warp >> 3;

    if (tid < 64) ((float*)(g + SM_BIAS))[tid] = bias[tid];

    // ---- load 4 halo lines (hi+lo): 130 rows x 64ci, SW128-swizzled ----
    {
        const int c8 = tid & 7;        // 16B ci-group
        const int jr = tid >> 3;       // 0..63
        for (int l = 0; l < 4; ++l) {
            const int gh = h0 + l - 1;
            const bool hok = (gh >= 0) && (gh < HH);
            const uint32_t bh = sb + (l * 2 + 0) * ABUF;
            const uint32_t bl = sb + (l * 2 + 1) * ABUF;
#pragma unroll
            for (int it = 0; it < 3; ++it) {
                int j = it * 64 + jr;          // 0..191
                if (j < 130) {
                    int gw = w0 - 1 + j;
                    uint4 vh = make_uint4(0, 0, 0, 0), vl = make_uint4(0, 0, 0, 0);
                    if (hok && gw >= 0 && gw < WW) {
                        size_t o = (((size_t)b * HH + gh) * WW + gw) * CIN + c8 * 8;
                        vh = *(const uint4*)&g_xhi[o];
                        vl = *(const uint4*)&g_xlo[o];
                    }
                    uint32_t so = SWZ((uint32_t)(j * 128 + c8 * 16));
                    STS128(bh + so, vh);
                    STS128(bl + so, vl);
                }
            }
        }
    }

    // ---- load B for tap 0 into buffer 0 ----
    {
        const char* src = (const char*)g_w + (size_t)(b * 9) * 16384;
#pragma unroll
        for (int i = 0; i < 2; ++i) {
            uint32_t o = (uint32_t)(i * NTH + tid) * 16;
            uint4 v = *(const uint4*)(src + o);
            STS128(sb + SM_B + (o & 8192) + SWZ(o & 8191), v);
        }
    }
    __syncthreads();

    // ---- accumulators: accP bias-initialized, accQ zero ----
    float accP[2][4][4], accQ[2][4][4];
    {
        const float* biasS = (const float*)(g + SM_BIAS);
#pragma unroll
        for (int nb = 0; nb < 4; ++nb) {
            float b0 = biasS[cohalf * 32 + nb * 8 + (lane & 3) * 2];
            float b1 = biasS[cohalf * 32 + nb * 8 + (lane & 3) * 2 + 1];
#pragma unroll
            for (int mh = 0; mh < 2; ++mh) {
                accP[mh][nb][0] = b0; accP[mh][nb][1] = b1;
                accP[mh][nb][2] = b0; accP[mh][nb][3] = b1;
                accQ[mh][nb][0] = 0.f; accQ[mh][nb][1] = 0.f;
                accQ[mh][nb][2] = 0.f; accQ[mh][nb][3] = 0.f;
            }
        }
    }

    // per-lane ldmatrix address components
    const int arow = lane & 15;
    const uint32_t acoff = (uint32_t)(lane >> 4) * 16;
    const int brow = (lane & 7) + (lane >> 4) * 8;
    const uint32_t bcoff = (uint32_t)((lane >> 3) & 1) * 16;

    for (int tap = 0; tap < 9; ++tap) {
        const int cur = tap & 1;
        const int kh = tap / 3, kw = tap - kh * 3;

        // prefetch next tap's B into registers
        uint4 pf[2];
        if (tap < 8) {
            const char* src = (const char*)g_w + (size_t)(b * 9 + tap + 1) * 16384;
#pragma unroll
            for (int i = 0; i < 2; ++i)
                pf[i] = *(const uint4*)(src + (uint32_t)(i * NTH + tid) * 16);
        }

        const uint32_t aH = sb + (uint32_t)((hline + kh) * 2 + 0) * ABUF;
        const uint32_t aL = aH + ABUF;
        const uint32_t bH = sb + SM_B + (uint32_t)cur * 16384;
        const uint32_t bL = bH + 8192;
        const int r0 = wchunk * 32 + kw + arow;       // + mh*16, max 129

#pragma unroll
        for (int kc = 0; kc < 4; ++kc) {
            const uint32_t co = (uint32_t)kc * 32 + acoff;
            uint32_t ah[2][4], al[2][4];
#pragma unroll
            for (int mh = 0; mh < 2; ++mh) {
                uint32_t off = SWZ((uint32_t)((r0 + mh * 16) * 128) + co);
                LDSM4(ah[mh][0], ah[mh][1], ah[mh][2], ah[mh][3], aH + off);
                LDSM4(al[mh][0], al[mh][1], al[mh][2], al[mh][3], aL + off);
            }
#pragma unroll
            for (int nb2 = 0; nb2 < 2; ++nb2) {
                uint32_t boff = SWZ(
                    (uint32_t)((cohalf * 32 + nb2 * 16 + brow) * 128) +
                    (uint32_t)kc * 32 + bcoff);
                uint32_t bh[4], bl[4];
                LDSM4(bh[0], bh[1], bh[2], bh[3], bH + boff);
                LDSM4(bl[0], bl[1], bl[2], bl[3], bL + boff);
#pragma unroll
                for (int mh = 0; mh < 2; ++mh) {
                    mma16816(accP[mh][2 * nb2],     ah[mh], bh);      // Ah*Bh
                    mma16816(accP[mh][2 * nb2 + 1], ah[mh], bh + 2);
                    mma16816(accQ[mh][2 * nb2],     ah[mh], bl);      // Ah*Bl
                    mma16816(accQ[mh][2 * nb2 + 1], ah[mh], bl + 2);
                    mma16816(accQ[mh][2 * nb2],     al[mh], bh);      // Al*Bh
                    mma16816(accQ[mh][2 * nb2 + 1], al[mh], bh + 2);
                }
            }
        }

        if (tap < 8) {
            // store prefetched B into the other buffer; one sync per tap
#pragma unroll
            for (int i = 0; i < 2; ++i) {
                uint32_t o = (uint32_t)(i * NTH + tid) * 16;
                STS128(sb + SM_B + (uint32_t)(cur ^ 1) * 16384 + (o & 8192) +
                           SWZ(o & 8191),
                       pf[i]);
            }
            __syncthreads();
        }
    }

    // ---- epilogue: P+Q, direct coalesced-enough stores ----
    const int hgl = h0 + hline;
#pragma unroll
    for (int mh = 0; mh < 2; ++mh) {
        const int wgl = w0 + wchunk * 32 + mh * 16 + (lane >> 2);
#pragma unroll
        for (int nb = 0; nb < 4; ++nb) {
            const int n0 = cohalf * 32 + nb * 8 + (lane & 3) * 2;
            float* p = out + (((size_t)b * COUT + n0) * HH + hgl) * WW + wgl;
            p[0] = accP[mh][nb][0] + accQ[mh][nb][0];
            p[(size_t)HH * WW] = accP[mh][nb][1] + accQ[mh][nb][1];
            p[8] = accP[mh][nb][2] + accQ[mh][nb][2];
            p[(size_t)HH * WW + 8] = accP[mh][nb][3] + accQ[mh][nb][3];
        }
    }
}

// ---------------------------------------------------------------------------
// Launch. Inputs: x, alpha, weight, bias. Output: float32 NCHW.
// ---------------------------------------------------------------------------
extern "C" void kernel_launch(void* const* d_in, const int* in_sizes, int n_in,
                              void* d_out, int out_size) {
    const float* x      = (const float*)d_in[0];
    const float* alpha  = (const float*)d_in[1];
    const float* weight = (const float*)d_in[2];
    const float* bias   = (const float*)d_in[3];
    float* out = (float*)d_out;
    (void)in_sizes; (void)n_in; (void)out_size;

    cudaFuncSetAttribute(conv_mma_kernel,
                         cudaFuncAttributeMaxDynamicSharedMemorySize, SMEM_REQ);

    xcvt_kernel<<<dim3(HH, BB), 256>>>(x);
    {
        int n = BB * 9 * COUT * CIN;
        wcvt_kernel<<<(n + 255) / 256, 256>>>(weight, alpha);
    }
    conv_mma_kernel<<<dim3(2, 128, BB), NTH, SMEM_REQ>>>(bias, out);
}